// round 11
// baseline (speedup 1.0000x reference)
#include <cuda_runtime.h>
#include <cstdint>

// Problem constants
#define B_TOTAL  128
#define C_IN     32
#define C_OUT    8
#define S_TOTAL  8192

// Tiling for fused kernel
#define S_TILE    32     // s-values per block = 8 float4 groups
#define SG        8      // float4 groups per block
#define B_PER_BLK 32     // batches per block (2 per thread)
#define THREADS   128

#define NPART     4      // ws partial-sum split

// Scratch: partial ws sums, g_wsp[p][j][s] = sum_{i in p-th chunk} w1[i][j][s]
__device__ float g_wsp[NPART][C_IN * S_TOTAL];

// ---------------------------------------------------------------------------
// helpers
// ---------------------------------------------------------------------------
__device__ __forceinline__ float tanh_fast(float x) {
    float y;
    asm("tanh.approx.f32 %0, %1;" : "=f"(y) : "f"(x));
    return y;
}

// Accurate tanh for final output: tanh(x) = 1 - 2/(e^{2x}+1)
__device__ __forceinline__ float tanh_acc(float x) {
    float xc = fminf(fmaxf(x, -20.0f), 20.0f);
    float e  = __expf(2.0f * xc);
    float r  = __frcp_rn(e + 1.0f);
    return fmaf(-2.0f, r, 1.0f);
}

__device__ __forceinline__ float4 ld4(const float* p) {
    return *reinterpret_cast<const float4*>(p);
}

__device__ __forceinline__ float4 tanh4_of_prod(float4 a, float4 b) {
    float4 r;
    r.x = tanh_fast(a.x * b.x);
    r.y = tanh_fast(a.y * b.y);
    r.z = tanh_fast(a.z * b.z);
    r.w = tanh_fast(a.w * b.w);
    return r;
}

__device__ __forceinline__ void fma4(float4& acc, float4 h, float4 w) {
    acc.x = fmaf(h.x, w.x, acc.x);
    acc.y = fmaf(h.y, w.y, acc.y);
    acc.z = fmaf(h.z, w.z, acc.z);
    acc.w = fmaf(h.w, w.w, acc.w);
}

// ---------------------------------------------------------------------------
// Kernel 1: partial ws sums. Thread -> (part, j, two adjacent f4 groups);
// sums 8 i values with 16 outstanding LDG.128 (MLP=16).
// w1: [C_IN(i)][C_IN(j)][S].
// ---------------------------------------------------------------------------
__global__ __launch_bounds__(256) void ws_kernel(const float* __restrict__ w1) {
    int t = blockIdx.x * blockDim.x + threadIdx.x;   // 0 .. NPART*C_IN*S/8-1
    int part = t >> 15;            // 32768 tasks per part
    int r    = t & 32767;
    int j    = r >> 10;            // 1024 double-group tasks per j row
    int grp  = r & 1023;           // covers f4 groups 2*grp, 2*grp+1
    const float* p = w1 + ((size_t)(part * 8) * C_IN + (size_t)j) * S_TOTAL + grp * 8;
    float4 a0 = make_float4(0.f, 0.f, 0.f, 0.f);
    float4 a1 = a0;
#pragma unroll
    for (int i = 0; i < 8; i++) {
        float4 v0 = ld4(p + (size_t)i * C_IN * S_TOTAL);
        float4 v1 = ld4(p + (size_t)i * C_IN * S_TOTAL + 4);
        a0.x += v0.x; a0.y += v0.y; a0.z += v0.z; a0.w += v0.w;
        a1.x += v1.x; a1.y += v1.y; a1.z += v1.z; a1.w += v1.w;
    }
    float* q = &g_wsp[part][(size_t)j * S_TOTAL + grp * 8];
    *reinterpret_cast<float4*>(q)     = a0;
    *reinterpret_cast<float4*>(q + 4) = a1;
}

// ---------------------------------------------------------------------------
// Kernel 2: fused stage1 + stage2, no h exchange, 2 batches per thread.
//
// Thread = (sg = t&7, bt = t>>3). Handles batches b0 = y*32+bt, b1 = b0+16.
// Per j: 2 LDG.128 (x), 1 LDS.128 (ws), 8 LDS.128 (w2) -> 16 fma4.
// w2/ws tiles in smem once per block, reused across 32 batches.
// __launch_bounds__(128, 5): target <=102 regs -> 5 CTAs/SM = 20 warps.
// Unroll 2 + incremental x pointers + zero-init acc (bias in epilogue)
// keep peak liveness under the cap.
// ---------------------------------------------------------------------------
__global__ void __launch_bounds__(THREADS, 5) fused_kernel(
    const float* __restrict__ x,     // [B][C_IN][S]
    const float* __restrict__ w2,    // [C_OUT][C_IN][S]
    const float* __restrict__ bias,  // [C_OUT][S]
    float* __restrict__ out)         // [B][C_OUT][S]
{
    __shared__ float4 w2s[C_OUT * C_IN * SG];  // 2048 f4 = 32 KB
    __shared__ float4 wss[C_IN * SG];          //  256 f4 =  4 KB

    const int t     = threadIdx.x;
    const int sBase = blockIdx.x * S_TILE;
    const int bt    = t >> 3;                  // 0..15
    const int sg    = t & 7;                   // 0..7
    const int b0    = blockIdx.y * B_PER_BLK + bt;

    // ---- preamble: cooperative smem fill ----
#pragma unroll
    for (int k = 0; k < (C_OUT * C_IN * SG) / THREADS; k++) {   // 16 iters
        int idx = t + k * THREADS;
        int row = idx >> 3;           // o*32 + j
        int sgl = idx & 7;
        w2s[idx] = ld4(w2 + (size_t)row * S_TOTAL + sBase + sgl * 4);
    }
#pragma unroll
    for (int k = 0; k < (C_IN * SG) / THREADS; k++) {           // 2 iters
        int idx = t + k * THREADS;
        int row = idx >> 3;
        int sgl = idx & 7;
        size_t off = (size_t)row * S_TOTAL + sBase + sgl * 4;
        float4 a = ld4(&g_wsp[0][off]);
#pragma unroll
        for (int p = 1; p < NPART; p++) {
            float4 v = ld4(&g_wsp[p][off]);
            a.x += v.x; a.y += v.y; a.z += v.z; a.w += v.w;
        }
        wss[idx] = a;
    }
    __syncthreads();

    // ---- accumulators: zero-init; bias folded in at epilogue ----
    float4 acc0[C_OUT], acc1[C_OUT];
#pragma unroll
    for (int o = 0; o < C_OUT; o++) {
        acc0[o] = make_float4(0.f, 0.f, 0.f, 0.f);
        acc1[o] = make_float4(0.f, 0.f, 0.f, 0.f);
    }

    // ---- main loop over j (incremental pointers, unroll 2) ----
    const float* xp0 = x + ((size_t)b0 * C_IN) * S_TOTAL + sBase + sg * 4;
    const float* xp1 = xp0 + (size_t)16 * C_IN * S_TOTAL;   // batch b0+16
    const float4* wsp  = &wss[sg];
    const float4* w2p  = &w2s[sg];

#pragma unroll 2
    for (int j = 0; j < C_IN; j++) {
        float4 xv0 = ld4(xp0);
        float4 xv1 = ld4(xp1);
        xp0 += S_TOTAL;
        xp1 += S_TOTAL;
        float4 wsv = wsp[j * SG];
        float4 h0  = tanh4_of_prod(xv0, wsv);
        float4 h1  = tanh4_of_prod(xv1, wsv);
#pragma unroll
        for (int o = 0; o < C_OUT; o++) {
            float4 w = w2p[(o * C_IN + j) * SG];
            fma4(acc0[o], h0, w);
            fma4(acc1[o], h1, w);
        }
    }

    // ---- epilogue: add bias, outer tanh, store (both batches) ----
    float* op0 = out + ((size_t)b0 * C_OUT) * S_TOTAL + sBase + sg * 4;
    float* op1 = op0 + (size_t)16 * C_OUT * S_TOTAL;
    const float* bp = bias + sBase + sg * 4;
#pragma unroll
    for (int o = 0; o < C_OUT; o++) {
        float4 bv = ld4(bp + (size_t)o * S_TOTAL);
        float4 ov;
        ov.x = tanh_acc(acc0[o].x + bv.x);
        ov.y = tanh_acc(acc0[o].y + bv.y);
        ov.z = tanh_acc(acc0[o].z + bv.z);
        ov.w = tanh_acc(acc0[o].w + bv.w);
        *reinterpret_cast<float4*>(op0 + (size_t)o * S_TOTAL) = ov;
        float4 ov1;
        ov1.x = tanh_acc(acc1[o].x + bv.x);
        ov1.y = tanh_acc(acc1[o].y + bv.y);
        ov1.z = tanh_acc(acc1[o].z + bv.z);
        ov1.w = tanh_acc(acc1[o].w + bv.w);
        *reinterpret_cast<float4*>(op1 + (size_t)o * S_TOTAL) = ov1;
    }
}

// ---------------------------------------------------------------------------
// launch
// ---------------------------------------------------------------------------
extern "C" void kernel_launch(void* const* d_in, const int* in_sizes, int n_in,
                              void* d_out, int out_size) {
    const float* x    = (const float*)d_in[0];
    const float* w1   = (const float*)d_in[1];
    const float* w2   = (const float*)d_in[2];
    const float* bias = (const float*)d_in[3];
    float* out = (float*)d_out;

    // Kernel 1: 4-way partial ws sums, 2 f4 groups per thread (MLP=16)
    ws_kernel<<<(NPART * C_IN * S_TOTAL / 8) / 256, 256>>>(w1);

    // Kernel 2: fused stages
    dim3 grid(S_TOTAL / S_TILE, B_TOTAL / B_PER_BLK);   // (256, 4) = 1024 blocks
    fused_kernel<<<grid, THREADS>>>(x, w2, bias, out);
}

// round 12
// speedup vs baseline: 1.5139x; 1.5139x over previous
#include <cuda_runtime.h>
#include <cstdint>

// Problem constants
#define B_TOTAL  128
#define C_IN     32
#define C_OUT    8
#define S_TOTAL  8192

// Tiling for fused kernel
#define S_TILE    32     // s-values per block = 8 float4 groups
#define SG        8      // float4 groups per block
#define B_PER_BLK 32     // batches per block (2 per thread)
#define THREADS   128

#define NPART     4      // ws partial-sum split

typedef unsigned long long ull;

// Scratch: partial ws sums, g_wsp[p][j][s] = sum_{i in p-th chunk} w1[i][j][s]
__device__ float g_wsp[NPART][C_IN * S_TOTAL];

// ---------------------------------------------------------------------------
// helpers
// ---------------------------------------------------------------------------
__device__ __forceinline__ float tanh_fast(float x) {
    float y;
    asm("tanh.approx.f32 %0, %1;" : "=f"(y) : "f"(x));
    return y;
}

// Accurate tanh for final output: tanh(x) = 1 - 2/(e^{2x}+1)
__device__ __forceinline__ float tanh_acc(float x) {
    float xc = fminf(fmaxf(x, -20.0f), 20.0f);
    float e  = __expf(2.0f * xc);
    float r  = __frcp_rn(e + 1.0f);
    return fmaf(-2.0f, r, 1.0f);
}

__device__ __forceinline__ float4 ld4(const float* p) {
    return *reinterpret_cast<const float4*>(p);
}

__device__ __forceinline__ float4 tanh4_of_prod(float4 a, float4 b) {
    float4 r;
    r.x = tanh_fast(a.x * b.x);
    r.y = tanh_fast(a.y * b.y);
    r.z = tanh_fast(a.z * b.z);
    r.w = tanh_fast(a.w * b.w);
    return r;
}

// packed f32x2 FMA (Blackwell FFMA2, PTX-only)
__device__ __forceinline__ void fma2p(ull& acc, ull h, ull w) {
    asm("fma.rn.f32x2 %0, %1, %2, %0;" : "+l"(acc) : "l"(h), "l"(w));
}

struct u2 { ull lo, hi; };   // 4 packed floats (== float4 bits)

__device__ __forceinline__ void fma4p(u2& acc, const u2& h, const u2& w) {
    fma2p(acc.lo, h.lo, w.lo);
    fma2p(acc.hi, h.hi, w.hi);
}

// ---------------------------------------------------------------------------
// Kernel 1: partial ws sums. Thread -> (part, j, two adjacent f4 groups);
// sums 8 i values with 16 outstanding LDG.128 (MLP=16).
// w1: [C_IN(i)][C_IN(j)][S].
// ---------------------------------------------------------------------------
__global__ __launch_bounds__(256) void ws_kernel(const float* __restrict__ w1) {
    int t = blockIdx.x * blockDim.x + threadIdx.x;   // 0 .. NPART*C_IN*S/8-1
    int part = t >> 15;            // 32768 tasks per part
    int r    = t & 32767;
    int j    = r >> 10;            // 1024 double-group tasks per j row
    int grp  = r & 1023;           // covers f4 groups 2*grp, 2*grp+1
    const float* p = w1 + ((size_t)(part * 8) * C_IN + (size_t)j) * S_TOTAL + grp * 8;
    float4 a0 = make_float4(0.f, 0.f, 0.f, 0.f);
    float4 a1 = a0;
#pragma unroll
    for (int i = 0; i < 8; i++) {
        float4 v0 = ld4(p + (size_t)i * C_IN * S_TOTAL);
        float4 v1 = ld4(p + (size_t)i * C_IN * S_TOTAL + 4);
        a0.x += v0.x; a0.y += v0.y; a0.z += v0.z; a0.w += v0.w;
        a1.x += v1.x; a1.y += v1.y; a1.z += v1.z; a1.w += v1.w;
    }
    float* q = &g_wsp[part][(size_t)j * S_TOTAL + grp * 8];
    *reinterpret_cast<float4*>(q)     = a0;
    *reinterpret_cast<float4*>(q + 4) = a1;
}

// ---------------------------------------------------------------------------
// Kernel 2: fused stage1 + stage2, no h exchange, 2 batches per thread.
//
// Thread = (sg = t&7, bt = t>>3). Handles batches b0 = y*32+bt, b1 = b0+16.
// Per j: 2 LDG.128 (x), 1 LDS.128 (ws), 8 LDS.128 (w2) -> 32 FFMA2.
// w2/ws tiles in smem once per block, reused across 32 batches.
// __launch_bounds__(128, 4): 128 regs -> 4 CTAs/SM = 16 warps (R10 point).
// Accumulation uses packed fma.rn.f32x2 -> FFMA issue halved vs R10.
// ---------------------------------------------------------------------------
__global__ void __launch_bounds__(THREADS, 4) fused_kernel(
    const float* __restrict__ x,     // [B][C_IN][S]
    const float* __restrict__ w2,    // [C_OUT][C_IN][S]
    const float* __restrict__ bias,  // [C_OUT][S]
    float* __restrict__ out)         // [B][C_OUT][S]
{
    __shared__ float4 w2s[C_OUT * C_IN * SG];  // 2048 f4 = 32 KB
    __shared__ float4 wss[C_IN * SG];          //  256 f4 =  4 KB

    const int t     = threadIdx.x;
    const int sBase = blockIdx.x * S_TILE;
    const int bt    = t >> 3;                  // 0..15
    const int sg    = t & 7;                   // 0..7
    const int b0    = blockIdx.y * B_PER_BLK + bt;
    const int b1    = b0 + 16;

    // ---- preamble: cooperative smem fill ----
#pragma unroll
    for (int k = 0; k < (C_OUT * C_IN * SG) / THREADS; k++) {   // 16 iters
        int idx = t + k * THREADS;
        int row = idx >> 3;           // o*32 + j
        int sgl = idx & 7;
        w2s[idx] = ld4(w2 + (size_t)row * S_TOTAL + sBase + sgl * 4);
    }
#pragma unroll
    for (int k = 0; k < (C_IN * SG) / THREADS; k++) {           // 2 iters
        int idx = t + k * THREADS;
        int row = idx >> 3;
        int sgl = idx & 7;
        size_t off = (size_t)row * S_TOTAL + sBase + sgl * 4;
        float4 a = ld4(&g_wsp[0][off]);
#pragma unroll
        for (int p = 1; p < NPART; p++) {
            float4 v = ld4(&g_wsp[p][off]);
            a.x += v.x; a.y += v.y; a.z += v.z; a.w += v.w;
        }
        wss[idx] = a;
    }
    __syncthreads();

    // ---- accumulators init from bias (same bias for both batches) ----
    u2 acc0[C_OUT], acc1[C_OUT];
#pragma unroll
    for (int o = 0; o < C_OUT; o++) {
        float4 bv = ld4(bias + (size_t)o * S_TOTAL + sBase + sg * 4);
        acc0[o] = *reinterpret_cast<const u2*>(&bv);
        acc1[o] = acc0[o];
    }

    // ---- main loop over j ----
    const float* xp0 = x + ((size_t)b0 * C_IN) * S_TOTAL + sBase + sg * 4;
    const float* xp1 = x + ((size_t)b1 * C_IN) * S_TOTAL + sBase + sg * 4;
#pragma unroll 4
    for (int j = 0; j < C_IN; j++) {
        float4 xv0 = ld4(xp0 + (size_t)j * S_TOTAL);
        float4 xv1 = ld4(xp1 + (size_t)j * S_TOTAL);
        float4 wsv = wss[j * SG + sg];
        float4 h0f = tanh4_of_prod(xv0, wsv);
        float4 h1f = tanh4_of_prod(xv1, wsv);
        u2 h0 = *reinterpret_cast<const u2*>(&h0f);
        u2 h1 = *reinterpret_cast<const u2*>(&h1f);
#pragma unroll
        for (int o = 0; o < C_OUT; o++) {
            u2 w = *reinterpret_cast<const u2*>(&w2s[(o * C_IN + j) * SG + sg]);
            fma4p(acc0[o], h0, w);
            fma4p(acc1[o], h1, w);
        }
    }

    // ---- epilogue: outer tanh + store (both batches) ----
    float* op0 = out + ((size_t)b0 * C_OUT) * S_TOTAL + sBase + sg * 4;
    float* op1 = out + ((size_t)b1 * C_OUT) * S_TOTAL + sBase + sg * 4;
#pragma unroll
    for (int o = 0; o < C_OUT; o++) {
        float4 a0 = *reinterpret_cast<const float4*>(&acc0[o]);
        float4 ov;
        ov.x = tanh_acc(a0.x);
        ov.y = tanh_acc(a0.y);
        ov.z = tanh_acc(a0.z);
        ov.w = tanh_acc(a0.w);
        *reinterpret_cast<float4*>(op0 + (size_t)o * S_TOTAL) = ov;
        float4 a1 = *reinterpret_cast<const float4*>(&acc1[o]);
        float4 ov1;
        ov1.x = tanh_acc(a1.x);
        ov1.y = tanh_acc(a1.y);
        ov1.z = tanh_acc(a1.z);
        ov1.w = tanh_acc(a1.w);
        *reinterpret_cast<float4*>(op1 + (size_t)o * S_TOTAL) = ov1;
    }
}

// ---------------------------------------------------------------------------
// launch
// ---------------------------------------------------------------------------
extern "C" void kernel_launch(void* const* d_in, const int* in_sizes, int n_in,
                              void* d_out, int out_size) {
    const float* x    = (const float*)d_in[0];
    const float* w1   = (const float*)d_in[1];
    const float* w2   = (const float*)d_in[2];
    const float* bias = (const float*)d_in[3];
    float* out = (float*)d_out;

    // Kernel 1: 4-way partial ws sums, 2 f4 groups per thread (MLP=16)
    ws_kernel<<<(NPART * C_IN * S_TOTAL / 8) / 256, 256>>>(w1);

    // Kernel 2: fused stages
    dim3 grid(S_TOTAL / S_TILE, B_TOTAL / B_PER_BLK);   // (256, 4) = 1024 blocks
    fused_kernel<<<grid, THREADS>>>(x, w2, bias, out);
}

// round 13
// speedup vs baseline: 1.5635x; 1.0328x over previous
#include <cuda_runtime.h>
#include <cstdint>

// Problem constants
#define B_TOTAL  128
#define C_IN     32
#define C_OUT    8
#define S_TOTAL  8192

// Tiling
#define S_TILE    32     // s-values per block = 8 float4 groups
#define SG        8      // float4 groups per block
#define B_PER_BLK 32     // batches per block (2 per thread)
#define THREADS   128

typedef unsigned long long ull;

// ---------------------------------------------------------------------------
// helpers
// ---------------------------------------------------------------------------
__device__ __forceinline__ float tanh_fast(float x) {
    float y;
    asm("tanh.approx.f32 %0, %1;" : "=f"(y) : "f"(x));
    return y;
}

__device__ __forceinline__ float4 ld4(const float* p) {
    return *reinterpret_cast<const float4*>(p);
}

__device__ __forceinline__ float4 tanh4_of_prod(float4 a, float4 b) {
    float4 r;
    r.x = tanh_fast(a.x * b.x);
    r.y = tanh_fast(a.y * b.y);
    r.z = tanh_fast(a.z * b.z);
    r.w = tanh_fast(a.w * b.w);
    return r;
}

// packed f32x2 FMA (Blackwell FFMA2, PTX-only)
__device__ __forceinline__ void fma2p(ull& acc, ull h, ull w) {
    asm("fma.rn.f32x2 %0, %1, %2, %0;" : "+l"(acc) : "l"(h), "l"(w));
}

struct u2 { ull lo, hi; };   // 4 packed floats (== float4 bits)

__device__ __forceinline__ void fma4p(u2& acc, const u2& h, const u2& w) {
    fma2p(acc.lo, h.lo, w.lo);
    fma2p(acc.hi, h.hi, w.hi);
}

// ---------------------------------------------------------------------------
// Single fused kernel: ws reduction (preamble) + stage1 + stage2.
//
// Preamble:
//   wss[j][sg] = sum_i w1[i][j][s4]   (each thread computes 2 f4 columns,
//                                      64 LDG.128, coalesced 128B per 8 lanes)
//   w2s = w2 tile (16 LDG.128 per thread)
// Mainloop (per thread, 2 batches b0/b0+16):
//   per j: 2 LDG.128 (x), 1 LDS.128 (ws), 8 LDS.128 (w2) -> 32 FFMA2
// Epilogue: outer tanh via tanh.approx (rel err ~1e-4 << 1e-3 threshold).
// __launch_bounds__(128, 4): 128 regs -> 4 CTAs/SM = 16 warps.
// ---------------------------------------------------------------------------
__global__ void __launch_bounds__(THREADS, 4) fused_kernel(
    const float* __restrict__ x,     // [B][C_IN][S]
    const float* __restrict__ w1,    // [C_IN][C_IN][S]
    const float* __restrict__ w2,    // [C_OUT][C_IN][S]
    const float* __restrict__ bias,  // [C_OUT][S]
    float* __restrict__ out)         // [B][C_OUT][S]
{
    __shared__ float4 w2s[C_OUT * C_IN * SG];  // 2048 f4 = 32 KB
    __shared__ float4 wss[C_IN * SG];          //  256 f4 =  4 KB

    const int t     = threadIdx.x;
    const int sBase = blockIdx.x * S_TILE;
    const int bt    = t >> 3;                  // 0..15
    const int sg    = t & 7;                   // 0..7
    const int b0    = blockIdx.y * B_PER_BLK + bt;
    const int b1    = b0 + 16;

    // ---- preamble A: w2 tile -> smem ----
#pragma unroll
    for (int k = 0; k < (C_OUT * C_IN * SG) / THREADS; k++) {   // 16 iters
        int idx = t + k * THREADS;
        int row = idx >> 3;           // o*32 + j
        int sgl = idx & 7;
        w2s[idx] = ld4(w2 + (size_t)row * S_TOTAL + sBase + sgl * 4);
    }

    // ---- preamble B: ws tile computed from w1 (k1 folded in) ----
#pragma unroll
    for (int k = 0; k < (C_IN * SG) / THREADS; k++) {           // 2 iters
        int idx = t + k * THREADS;
        int j   = idx >> 3;
        int sgl = idx & 7;
        const float* p = w1 + (size_t)j * S_TOTAL + sBase + sgl * 4;
        float4 a = make_float4(0.f, 0.f, 0.f, 0.f);
#pragma unroll 8
        for (int i = 0; i < C_IN; i++) {
            float4 v = ld4(p + (size_t)i * C_IN * S_TOTAL);
            a.x += v.x; a.y += v.y; a.z += v.z; a.w += v.w;
        }
        wss[idx] = a;
    }
    __syncthreads();

    // ---- accumulators init from bias (same bias for both batches) ----
    u2 acc0[C_OUT], acc1[C_OUT];
#pragma unroll
    for (int o = 0; o < C_OUT; o++) {
        float4 bv = ld4(bias + (size_t)o * S_TOTAL + sBase + sg * 4);
        acc0[o] = *reinterpret_cast<const u2*>(&bv);
        acc1[o] = acc0[o];
    }

    // ---- main loop over j ----
    const float* xp0 = x + ((size_t)b0 * C_IN) * S_TOTAL + sBase + sg * 4;
    const float* xp1 = x + ((size_t)b1 * C_IN) * S_TOTAL + sBase + sg * 4;
#pragma unroll 4
    for (int j = 0; j < C_IN; j++) {
        float4 xv0 = ld4(xp0 + (size_t)j * S_TOTAL);
        float4 xv1 = ld4(xp1 + (size_t)j * S_TOTAL);
        float4 wsv = wss[j * SG + sg];
        float4 h0f = tanh4_of_prod(xv0, wsv);
        float4 h1f = tanh4_of_prod(xv1, wsv);
        u2 h0 = *reinterpret_cast<const u2*>(&h0f);
        u2 h1 = *reinterpret_cast<const u2*>(&h1f);
#pragma unroll
        for (int o = 0; o < C_OUT; o++) {
            u2 w = *reinterpret_cast<const u2*>(&w2s[(o * C_IN + j) * SG + sg]);
            fma4p(acc0[o], h0, w);
            fma4p(acc1[o], h1, w);
        }
    }

    // ---- epilogue: outer tanh (approx) + store (both batches) ----
    float* op0 = out + ((size_t)b0 * C_OUT) * S_TOTAL + sBase + sg * 4;
    float* op1 = out + ((size_t)b1 * C_OUT) * S_TOTAL + sBase + sg * 4;
#pragma unroll
    for (int o = 0; o < C_OUT; o++) {
        float4 a0 = *reinterpret_cast<const float4*>(&acc0[o]);
        float4 ov;
        ov.x = tanh_fast(a0.x);
        ov.y = tanh_fast(a0.y);
        ov.z = tanh_fast(a0.z);
        ov.w = tanh_fast(a0.w);
        *reinterpret_cast<float4*>(op0 + (size_t)o * S_TOTAL) = ov;
        float4 a1 = *reinterpret_cast<const float4*>(&acc1[o]);
        float4 ov1;
        ov1.x = tanh_fast(a1.x);
        ov1.y = tanh_fast(a1.y);
        ov1.z = tanh_fast(a1.z);
        ov1.w = tanh_fast(a1.w);
        *reinterpret_cast<float4*>(op1 + (size_t)o * S_TOTAL) = ov1;
    }
}

// ---------------------------------------------------------------------------
// launch
// ---------------------------------------------------------------------------
extern "C" void kernel_launch(void* const* d_in, const int* in_sizes, int n_in,
                              void* d_out, int out_size) {
    const float* x    = (const float*)d_in[0];
    const float* w1   = (const float*)d_in[1];
    const float* w2   = (const float*)d_in[2];
    const float* bias = (const float*)d_in[3];
    float* out = (float*)d_out;

    dim3 grid(S_TOTAL / S_TILE, B_TOTAL / B_PER_BLK);   // (256, 4) = 1024 blocks
    fused_kernel<<<grid, THREADS>>>(x, w1, w2, bias, out);
}